// round 1
// baseline (speedup 1.0000x reference)
#include <cuda_runtime.h>

// 4-qubit, depth-2 variational circuit over B=2^20 samples.
// Strategy:
//   1) prep_kernel (1 block, 16 threads): build the batch-independent 16x16
//      complex unitary U for the variational layers (CNOT ring + RY/RZ x2)
//      from `weights`, store in __device__ global g_U (float2 re/im).
//   2) main_kernel: one thread per sample. Embedded state is a REAL product
//      state psi_s = prod_w v_w[bit_w], v_w = (cos(x_w*pi/2), sin(x_w*pi/2)).
//      amp = U * psi (real vec x complex mat, 512 FMA), probs, signed Z sums.
// Bit convention (matches PennyLane/reference): wire w = bit (3-w) of the
// flat state index s, i.e. mask_w = 8 >> w.

__device__ float2 g_U[256];  // g_U[s*16 + j] = U[s][j] (re, im)

__global__ void qc_prep_kernel(const float* __restrict__ w) {
    int j = threadIdx.x;  // column index: circuit applied to basis |j>
    if (j >= 16) return;
    float re[16], im[16];
#pragma unroll
    for (int s = 0; s < 16; ++s) { re[s] = (s == j) ? 1.0f : 0.0f; im[s] = 0.0f; }

    const int ctrl[4] = {0, 1, 2, 3};
    const int targ[4] = {1, 2, 3, 0};

    for (int d = 0; d < 2; ++d) {
        // CNOT ring
        for (int g = 0; g < 4; ++g) {
            int cm = 8 >> ctrl[g];
            int tm = 8 >> targ[g];
            float tre[16], tim[16];
            for (int s = 0; s < 16; ++s) {
                int src = (s & cm) ? (s ^ tm) : s;
                tre[s] = re[src]; tim[s] = im[src];
            }
            for (int s = 0; s < 16; ++s) { re[s] = tre[s]; im[s] = tim[s]; }
        }
        // Per-qubit RY then RZ
        for (int q = 0; q < 4; ++q) {
            int m = 8 >> q;
            float th = w[d * 8 + q * 2 + 0];
            float cy, sy;
            sincosf(0.5f * th, &sy, &cy);
            for (int s = 0; s < 16; ++s) {
                if (s & m) continue;
                int s1 = s | m;
                float r0 = re[s], i0 = im[s], r1 = re[s1], i1 = im[s1];
                re[s]  = cy * r0 - sy * r1;  im[s]  = cy * i0 - sy * i1;
                re[s1] = sy * r0 + cy * r1;  im[s1] = sy * i0 + cy * i1;
            }
            float ph = w[d * 8 + q * 2 + 1];
            float cp, sp;
            sincosf(0.5f * ph, &sp, &cp);
            for (int s = 0; s < 16; ++s) {
                float r = re[s], i = im[s];
                if (s & m) {
                    // e^{+i ph/2}
                    re[s] = r * cp - i * sp;  im[s] = i * cp + r * sp;
                } else {
                    // e^{-i ph/2}
                    re[s] = r * cp + i * sp;  im[s] = i * cp - r * sp;
                }
            }
        }
    }
#pragma unroll
    for (int s = 0; s < 16; ++s) g_U[s * 16 + j] = make_float2(re[s], im[s]);
}

__global__ void __launch_bounds__(256) qc_main_kernel(
    const float4* __restrict__ x, float4* __restrict__ out, int B) {
    __shared__ float2 Us[256];
    int tid = threadIdx.x;
    Us[tid] = g_U[tid];
    __syncthreads();

    int i = blockIdx.x * 256 + tid;
    if (i >= B) return;

    float4 xv = x[i];
    const float HPI = 1.57079632679489662f;  // pi/2 (RY half-angle of x*pi)
    float c0, s0, c1, s1, c2, s2, c3, s3;
    __sincosf(xv.x * HPI, &s0, &c0);
    __sincosf(xv.y * HPI, &s1, &c1);
    __sincosf(xv.z * HPI, &s2, &c2);
    __sincosf(xv.w * HPI, &s3, &c3);

    // psi_s = v0[b0]*v1[b1]*v2[b2]*v3[b3], s = b0b1b2b3 (b0 MSB)
    float a01[4] = {c0 * c1, c0 * s1, s0 * c1, s0 * s1};  // index b0b1
    float a23[4] = {c2 * c3, c2 * s3, s2 * c3, s2 * s3};  // index b2b3
    float psi[16];
#pragma unroll
    for (int hi = 0; hi < 4; ++hi)
#pragma unroll
        for (int lo = 0; lo < 4; ++lo)
            psi[hi * 4 + lo] = a01[hi] * a23[lo];

    float z0 = 0.f, z1 = 0.f, z2 = 0.f, z3 = 0.f;
#pragma unroll
    for (int s = 0; s < 16; ++s) {
        float ar = 0.f, ai = 0.f;
#pragma unroll
        for (int jj = 0; jj < 16; ++jj) {
            float2 u = Us[s * 16 + jj];
            ar = fmaf(u.x, psi[jj], ar);
            ai = fmaf(u.y, psi[jj], ai);
        }
        float p = fmaf(ar, ar, ai * ai);
        z0 += (s & 8) ? -p : p;
        z1 += (s & 4) ? -p : p;
        z2 += (s & 2) ? -p : p;
        z3 += (s & 1) ? -p : p;
    }
    out[i] = make_float4(z0, z1, z2, z3);
}

extern "C" void kernel_launch(void* const* d_in, const int* in_sizes, int n_in,
                              void* d_out, int out_size) {
    const float* x = (const float*)d_in[0];       // [B,4]
    const float* w = (const float*)d_in[1];       // [2,4,2]
    float* out = (float*)d_out;                   // [B,4]
    int B = in_sizes[0] / 4;

    qc_prep_kernel<<<1, 16>>>(w);
    int blocks = (B + 255) / 256;
    qc_main_kernel<<<blocks, 256>>>((const float4*)x, (float4*)out, B);
}